// round 2
// baseline (speedup 1.0000x reference)
#include <cuda_runtime.h>
#include <cuda_bf16.h>

#define C_DIM 2048
#define R_DIM 1024
#define B_DIM 16

// Deduped selection indices (scratch — device globals per harness rules)
__device__ int g_sel_b[C_DIM];  // column selection: out col j reads input col g_sel_b[j]
__device__ int g_sel_r[R_DIM];  // row selection:    out row i reads input row g_sel_r[i]

// ---------------------------------------------------------------------------
// Prep: per weight vector, compute sel = round(clip(w,0,n-1)) and resolve
// duplicates: k-th duplicate (index order) -> k-th LARGEST unused value.
// One block per weight (block 0 = column/2048, block 1 = row/1024).
// ---------------------------------------------------------------------------
__global__ void prep_kernel(const float* __restrict__ wc,
                            const float* __restrict__ wr) {
    const int  n      = (blockIdx.x == 0) ? C_DIM : R_DIM;
    const float* w    = (blockIdx.x == 0) ? wc : wr;
    int*       outsel = (blockIdx.x == 0) ? g_sel_b : g_sel_r;

    __shared__ int sel[C_DIM];
    __shared__ int firstIdx[C_DIM];
    __shared__ int scanA[C_DIM];
    __shared__ int scanTmp[C_DIM];
    __shared__ int emptyByRank[C_DIM];
    __shared__ int sh_E;

    const int tid = threadIdx.x;
    const int nt  = blockDim.x;
    const float upper = (float)(n - 1);

    for (int i = tid; i < n; i += nt) {
        float v = fminf(fmaxf(w[i], 0.0f), upper);
        sel[i] = __float2int_rn(v);          // round-half-to-even, like jnp.round
        firstIdx[i] = 0x7fffffff;
    }
    __syncthreads();
    for (int i = tid; i < n; i += nt) atomicMin(&firstIdx[sel[i]], i);
    __syncthreads();

    // ---- pass 1: scan EMPTY flags over values -> emptyByRank (descending) ----
    for (int v = tid; v < n; v += nt)
        scanA[v] = (firstIdx[v] == 0x7fffffff) ? 1 : 0;
    __syncthreads();
    for (int off = 1; off < n; off <<= 1) {
        for (int i = tid; i < n; i += nt)
            scanTmp[i] = scanA[i] + ((i >= off) ? scanA[i - off] : 0);
        __syncthreads();
        for (int i = tid; i < n; i += nt) scanA[i] = scanTmp[i];
        __syncthreads();
    }
    if (tid == 0) sh_E = scanA[n - 1];       // total empties (== total dups)
    __syncthreads();
    const int E = sh_E;
    for (int v = tid; v < n; v += nt) {
        if (firstIdx[v] == 0x7fffffff) {
            int asc = scanA[v] - 1;          // ascending rank among empties
            emptyByRank[E - 1 - asc] = v;    // slot 0 = largest empty value
        }
    }
    __syncthreads();

    // ---- pass 2: scan DUP flags over indices -> duplicate rank ----
    for (int i = tid; i < n; i += nt)
        scanA[i] = (firstIdx[sel[i]] != i) ? 1 : 0;
    __syncthreads();
    for (int off = 1; off < n; off <<= 1) {
        for (int i = tid; i < n; i += nt)
            scanTmp[i] = scanA[i] + ((i >= off) ? scanA[i - off] : 0);
        __syncthreads();
        for (int i = tid; i < n; i += nt) scanA[i] = scanTmp[i];
        __syncthreads();
    }

    for (int i = tid; i < n; i += nt) {
        bool dup = (firstIdx[sel[i]] != i);
        outsel[i] = dup ? emptyByRank[scanA[i] - 1] : sel[i];
    }
}

// ---------------------------------------------------------------------------
// Gather: out[bt, i, j] = x[bt, r[i], b[j]].
// One block per output row. Coalesced float4 load of the source row into
// smem, coalesced float4 store of the permuted row. 512 threads = 512 float4.
// ---------------------------------------------------------------------------
__global__ void __launch_bounds__(512)
gather_kernel(const float* __restrict__ x, float* __restrict__ out) {
    const int row = blockIdx.x;              // bt * R_DIM + i
    const int bt  = row >> 10;               // / R_DIM
    const int i   = row & (R_DIM - 1);

    __shared__ float srow[C_DIM];

    const int r = g_sel_r[i];                // broadcast load, L1-cached
    const float4* src = (const float4*)(x + ((size_t)bt * R_DIM + r) * C_DIM);
    float4* s4 = (float4*)srow;

    const int t = threadIdx.x;               // 0..511, C_DIM/4 = 512
    s4[t] = src[t];
    __syncthreads();

    const int4 bj = ((const int4*)g_sel_b)[t];   // 4 column indices, L1-cached
    float4 v;
    v.x = srow[bj.x];
    v.y = srow[bj.y];
    v.z = srow[bj.z];
    v.w = srow[bj.w];
    ((float4*)(out + (size_t)row * C_DIM))[t] = v;
}

extern "C" void kernel_launch(void* const* d_in, const int* in_sizes, int n_in,
                              void* d_out, int out_size) {
    const float* x  = (const float*)d_in[0];   // [16, 1024, 2048] f32
    const float* wc = (const float*)d_in[1];   // [2048] f32
    const float* wr = (const float*)d_in[2];   // [1024] f32
    float* out = (float*)d_out;

    prep_kernel<<<2, 1024>>>(wc, wr);
    gather_kernel<<<B_DIM * R_DIM, 512>>>(x, out);
}

// round 3
// speedup vs baseline: 1.1465x; 1.1465x over previous
#include <cuda_runtime.h>
#include <cuda_bf16.h>

#define C_DIM 2048
#define R_DIM 1024
#define B_DIM 16

// Deduped selection indices (device-global scratch per harness rules)
__device__ int g_sel_b[C_DIM];  // out col j reads input col g_sel_b[j]
__device__ int g_sel_r[R_DIM];  // out row i reads input row g_sel_r[i]

// ---------------------------------------------------------------------------
// Fast block-wide inclusive scan (in-place over smem array a[0..n)).
// blockDim = 1024. n == 2048 (2 elems/thread) or n == 1024 (1 elem/thread).
// Two-level: warp shuffle scan -> warp-sum scan -> add back. 3 barriers.
// ---------------------------------------------------------------------------
__device__ __forceinline__ void block_scan(int* a, int n, int tid, int* wsum) {
    const int lane = tid & 31, wid = tid >> 5;
    int v0 = 0, v1 = 0;
    const int i0 = 2 * tid;
    if (n == 2048) { v0 = a[i0]; v1 = a[i0 + 1]; }
    else           { v0 = a[tid]; }
    int s = v0 + v1;
    #pragma unroll
    for (int off = 1; off < 32; off <<= 1) {
        int y = __shfl_up_sync(0xffffffffu, s, off);
        if (lane >= off) s += y;
    }
    if (lane == 31) wsum[wid] = s;
    __syncthreads();
    if (wid == 0) {
        int t = wsum[lane];
        #pragma unroll
        for (int off = 1; off < 32; off <<= 1) {
            int y = __shfl_up_sync(0xffffffffu, t, off);
            if (lane >= off) t += y;
        }
        wsum[lane] = t;
    }
    __syncthreads();
    const int excl = (wid ? wsum[wid - 1] : 0) + s - (v0 + v1);
    if (n == 2048) { a[i0] = excl + v0; a[i0 + 1] = excl + v0 + v1; }
    else           { a[tid] = excl + v0; }
    __syncthreads();
}

// ---------------------------------------------------------------------------
// Prep: sel = round(clip(w,0,n-1)); k-th duplicate (index order) is
// reassigned to the k-th LARGEST unused value. One block per weight vector.
// ---------------------------------------------------------------------------
__global__ void __launch_bounds__(1024)
prep_kernel(const float* __restrict__ wc, const float* __restrict__ wr) {
    const bool  isC    = (blockIdx.x == 0);
    const int   n      = isC ? C_DIM : R_DIM;
    const float* w     = isC ? wc : wr;
    int*        outsel = isC ? g_sel_b : g_sel_r;

    __shared__ int sel[C_DIM];
    __shared__ int firstIdx[C_DIM];
    __shared__ int scanA[C_DIM];
    __shared__ int emptyByRank[C_DIM];
    __shared__ int wsum[32];
    __shared__ int sh_E;

    const int tid   = threadIdx.x;     // 0..1023
    const float upper = (float)(n - 1);

    if (n == 2048) {
        const int i0 = 2 * tid;
        sel[i0]     = __float2int_rn(fminf(fmaxf(w[i0],     0.0f), upper));
        sel[i0 + 1] = __float2int_rn(fminf(fmaxf(w[i0 + 1], 0.0f), upper));
        firstIdx[i0] = 0x7fffffff; firstIdx[i0 + 1] = 0x7fffffff;
    } else {
        sel[tid] = __float2int_rn(fminf(fmaxf(w[tid], 0.0f), upper));
        firstIdx[tid] = 0x7fffffff;
    }
    __syncthreads();
    for (int i = tid; i < n; i += 1024) atomicMin(&firstIdx[sel[i]], i);
    __syncthreads();

    // ---- pass 1: scan EMPTY flags over values -> emptyByRank (descending) --
    for (int v = tid; v < n; v += 1024)
        scanA[v] = (firstIdx[v] == 0x7fffffff) ? 1 : 0;
    __syncthreads();
    block_scan(scanA, n, tid, wsum);
    if (tid == 0) sh_E = scanA[n - 1];          // total empties (== total dups)
    __syncthreads();
    const int E = sh_E;
    for (int v = tid; v < n; v += 1024) {
        if (firstIdx[v] == 0x7fffffff) {
            int asc = scanA[v] - 1;             // ascending rank among empties
            emptyByRank[E - 1 - asc] = v;       // slot 0 = largest empty value
        }
    }
    __syncthreads();

    // ---- pass 2: scan DUP flags over indices -> duplicate rank -------------
    for (int i = tid; i < n; i += 1024)
        scanA[i] = (firstIdx[sel[i]] != i) ? 1 : 0;
    __syncthreads();
    block_scan(scanA, n, tid, wsum);

    for (int i = tid; i < n; i += 1024) {
        bool dup = (firstIdx[sel[i]] != i);
        outsel[i] = dup ? emptyByRank[scanA[i] - 1] : sel[i];
    }
}

// ---------------------------------------------------------------------------
// Gather: out[bt, i, j] = x[bt, r[i], b[j]].
// 4 rows per 256-thread block: 8 independent LDG.128 per thread (MLP=8),
// column-index int4s loaded once and reused across the 4 rows, streaming
// loads/stores (zero reuse). 32KB smem -> 7 blocks/SM.
// ---------------------------------------------------------------------------
__global__ void __launch_bounds__(256)
gather_kernel(const float* __restrict__ x, float* __restrict__ out) {
    const int row0 = blockIdx.x << 2;        // first of 4 consecutive rows
    const int bt   = row0 >> 10;             // / R_DIM (R_DIM divisible by 4)
    const int i0   = row0 & (R_DIM - 1);

    __shared__ float srow[4][C_DIM];
    const int t = threadIdx.x;               // 0..255

    // Load 4 source rows; all 8 float4 loads independent -> deep MLP.
    #pragma unroll
    for (int k = 0; k < 4; k++) {
        const int r = g_sel_r[i0 + k];
        const float4* src =
            (const float4*)(x + ((size_t)(bt << 10) + r) * C_DIM);
        float4* s4 = (float4*)srow[k];
        s4[t]       = __ldcs(src + t);
        s4[t + 256] = __ldcs(src + t + 256);
    }
    __syncthreads();

    // Column indices: 2 int4 per thread, reused for all 4 rows.
    const int4 b0 = ((const int4*)g_sel_b)[t];
    const int4 b1 = ((const int4*)g_sel_b)[t + 256];

    #pragma unroll
    for (int k = 0; k < 4; k++) {
        const float* s = srow[k];
        float4* o = (float4*)(out + (size_t)(row0 + k) * C_DIM);
        float4 v;
        v.x = s[b0.x]; v.y = s[b0.y]; v.z = s[b0.z]; v.w = s[b0.w];
        __stwt(o + t, v);
        v.x = s[b1.x]; v.y = s[b1.y]; v.z = s[b1.z]; v.w = s[b1.w];
        __stwt(o + t + 256, v);
    }
}

extern "C" void kernel_launch(void* const* d_in, const int* in_sizes, int n_in,
                              void* d_out, int out_size) {
    const float* x  = (const float*)d_in[0];   // [16, 1024, 2048] f32
    const float* wc = (const float*)d_in[1];   // [2048] f32
    const float* wr = (const float*)d_in[2];   // [1024] f32
    float* out = (float*)d_out;

    prep_kernel<<<2, 1024>>>(wc, wr);
    gather_kernel<<<(B_DIM * R_DIM) / 4, 256>>>(x, out);
}

// round 4
// speedup vs baseline: 1.4675x; 1.2799x over previous
#include <cuda_runtime.h>
#include <cuda_bf16.h>
#include <cstdint>

#define C_DIM 2048
#define R_DIM 1024
#define B_DIM 16

#define ROWS_PER_BLOCK 16
#define CHUNK_ROWS 4
#define CHUNKS (ROWS_PER_BLOCK / CHUNK_ROWS)
#define CHUNK_BYTES (CHUNK_ROWS * C_DIM * 4)      /* 32768 */
#define SMEM_TOTAL (2 * CHUNK_BYTES + 64)          /* 2 buffers + mbarriers */

// Device-global scratch (no allocations allowed)
__device__ int g_sel_b[C_DIM];   // out col j reads input col g_sel_b[j]
__device__ int g_inv_r[R_DIM];   // input row q goes to output row g_inv_r[q]
__device__ int g_flag[2];        // prep-done flags (col, row); idempotent 0->1

// ---------------- PTX helpers ----------------
__device__ __forceinline__ uint32_t smem_u32(const void* p) {
    return (uint32_t)__cvta_generic_to_shared(p);
}
__device__ __forceinline__ void mbar_init(uint32_t a, uint32_t cnt) {
    asm volatile("mbarrier.init.shared.b64 [%0], %1;" :: "r"(a), "r"(cnt) : "memory");
}
__device__ __forceinline__ void mbar_expect_tx(uint32_t a, uint32_t bytes) {
    asm volatile("mbarrier.arrive.expect_tx.shared.b64 _, [%0], %1;"
                 :: "r"(a), "r"(bytes) : "memory");
}
__device__ __forceinline__ void mbar_wait(uint32_t a, uint32_t parity) {
    asm volatile(
        "{\n\t.reg .pred P;\n\t"
        "WAIT_%=:\n\t"
        "mbarrier.try_wait.parity.acquire.cta.shared::cta.b64 P, [%0], %1, 0x989680;\n\t"
        "@P bra.uni DONE_%=;\n\t"
        "bra.uni WAIT_%=;\n\t"
        "DONE_%=:\n\t}"
        :: "r"(a), "r"(parity) : "memory");
}
__device__ __forceinline__ void bulk_ld(uint32_t dst, const void* src,
                                        uint32_t bytes, uint32_t mbar) {
    asm volatile(
        "cp.async.bulk.shared::cluster.global.mbarrier::complete_tx::bytes [%0], [%1], %2, [%3];"
        :: "r"(dst), "l"(src), "r"(bytes), "r"(mbar) : "memory");
}

// ---------------- block-wide inclusive scan (1024 threads) ----------------
__device__ __forceinline__ void block_scan(int* a, int n, int tid, int* wsum) {
    const int lane = tid & 31, wid = tid >> 5;
    int v0 = 0, v1 = 0;
    const int i0 = 2 * tid;
    if (n == 2048) { v0 = a[i0]; v1 = a[i0 + 1]; }
    else           { v0 = a[tid]; }
    int s = v0 + v1;
    #pragma unroll
    for (int off = 1; off < 32; off <<= 1) {
        int y = __shfl_up_sync(0xffffffffu, s, off);
        if (lane >= off) s += y;
    }
    if (lane == 31) wsum[wid] = s;
    __syncthreads();
    if (wid == 0) {
        int t = wsum[lane];
        #pragma unroll
        for (int off = 1; off < 32; off <<= 1) {
            int y = __shfl_up_sync(0xffffffffu, t, off);
            if (lane >= off) t += y;
        }
        wsum[lane] = t;
    }
    __syncthreads();
    const int excl = (wid ? wsum[wid - 1] : 0) + s - (v0 + v1);
    if (n == 2048) { a[i0] = excl + v0; a[i0 + 1] = excl + v0 + v1; }
    else           { a[tid] = excl + v0; }
    __syncthreads();
}

// ---------------------------------------------------------------------------
// Fused kernel. Blocks 0,1: prep (dedup indices). Blocks 2..: TMA-pipelined
// scatter-by-row / gather-by-column. Gather blocks start their loads
// immediately (loads depend only on the block's fixed input rows) and only
// spin for the prep flags before the store phase.
// ---------------------------------------------------------------------------
__global__ void __launch_bounds__(1024, 2)
fused_kernel(const float* __restrict__ x, const float* __restrict__ wc,
             const float* __restrict__ wr, float* __restrict__ out)
{
    extern __shared__ char smem[];
    const int tid = threadIdx.x;

    if (blockIdx.x < 2) {
        // ================= PREP =================
        const bool  isC = (blockIdx.x == 0);
        const int   n   = isC ? C_DIM : R_DIM;
        const float* w  = isC ? wc : wr;

        int* sel         = (int*)smem;
        int* firstIdx    = sel + C_DIM;
        int* scanA       = firstIdx + C_DIM;
        int* emptyByRank = scanA + C_DIM;
        __shared__ int wsum[32];
        __shared__ int sh_E;

        const float upper = (float)(n - 1);
        if (n == 2048) {
            const int i0 = 2 * tid;
            sel[i0]     = __float2int_rn(fminf(fmaxf(w[i0],     0.0f), upper));
            sel[i0 + 1] = __float2int_rn(fminf(fmaxf(w[i0 + 1], 0.0f), upper));
            firstIdx[i0] = 0x7fffffff; firstIdx[i0 + 1] = 0x7fffffff;
        } else {
            sel[tid] = __float2int_rn(fminf(fmaxf(w[tid], 0.0f), upper));
            firstIdx[tid] = 0x7fffffff;
        }
        __syncthreads();
        for (int i = tid; i < n; i += 1024) atomicMin(&firstIdx[sel[i]], i);
        __syncthreads();

        // pass 1: scan EMPTY flags over values -> emptyByRank (descending)
        for (int v = tid; v < n; v += 1024)
            scanA[v] = (firstIdx[v] == 0x7fffffff) ? 1 : 0;
        __syncthreads();
        block_scan(scanA, n, tid, wsum);
        if (tid == 0) sh_E = scanA[n - 1];
        __syncthreads();
        const int E = sh_E;
        for (int v = tid; v < n; v += 1024) {
            if (firstIdx[v] == 0x7fffffff) {
                int asc = scanA[v] - 1;
                emptyByRank[E - 1 - asc] = v;   // slot 0 = largest empty value
            }
        }
        __syncthreads();

        // pass 2: scan DUP flags over indices -> duplicate rank
        for (int i = tid; i < n; i += 1024)
            scanA[i] = (firstIdx[sel[i]] != i) ? 1 : 0;
        __syncthreads();
        block_scan(scanA, n, tid, wsum);

        for (int i = tid; i < n; i += 1024) {
            bool dup = (firstIdx[sel[i]] != i);
            int v = dup ? emptyByRank[scanA[i] - 1] : sel[i];
            if (isC) g_sel_b[i] = v;     // column gather index
            else     g_inv_r[v] = i;     // inverse row permutation (v is a perm)
        }
        __threadfence();
        __syncthreads();
        if (tid == 0) {
            int* f = &g_flag[isC ? 0 : 1];
            asm volatile("st.release.gpu.global.b32 [%0], %1;"
                         :: "l"(f), "r"(1) : "memory");
        }
        return;
    }

    // ================= GATHER / SCATTER =================
    const int q0 = (int)(blockIdx.x - 2) * ROWS_PER_BLOCK;   // first input row
    const uint32_t sbase = smem_u32(smem);
    const uint32_t mbar0 = sbase + 2 * CHUNK_BYTES;
    const uint32_t mbar1 = mbar0 + 8;

    if (tid == 0) {
        mbar_init(mbar0, 1);
        mbar_init(mbar1, 1);
        asm volatile("fence.proxy.async.shared::cta;" ::: "memory");
        // Prologue: two chunks in flight before anything else.
        mbar_expect_tx(mbar0, CHUNK_BYTES);
        bulk_ld(sbase, x + (size_t)q0 * C_DIM, CHUNK_BYTES, mbar0);
        mbar_expect_tx(mbar1, CHUNK_BYTES);
        bulk_ld(sbase + CHUNK_BYTES,
                x + (size_t)(q0 + CHUNK_ROWS) * C_DIM, CHUNK_BYTES, mbar1);
        // Wait for prep (overlapped with the loads above).
        int a, b;
        do {
            asm volatile("ld.acquire.gpu.global.b32 %0, [%1];" : "=r"(a) : "l"(&g_flag[0]));
            asm volatile("ld.acquire.gpu.global.b32 %0, [%1];" : "=r"(b) : "l"(&g_flag[1]));
        } while (!(a && b));
    }
    __syncthreads();

    // Per-thread fixed column slot: c4 in [0,512), rows k0 and k0+2 per chunk.
    const int c4 = tid & 511;
    const int k0 = tid >> 9;                       // 0 or 1
    const int4 bj = ((const int4*)g_sel_b)[c4];    // reused across all chunks

    #pragma unroll
    for (int c = 0; c < CHUNKS; c++) {
        const uint32_t mb = (c & 1) ? mbar1 : mbar0;
        mbar_wait(mb, (c >> 1) & 1);
        const float* buf = (const float*)(smem + (c & 1) * CHUNK_BYTES);

        #pragma unroll
        for (int s = 0; s < 2; s++) {
            const int k = k0 + s * 2;
            const int Q = q0 + c * CHUNK_ROWS + k;           // input row (flat)
            const int orow = (Q & ~(R_DIM - 1)) | g_inv_r[Q & (R_DIM - 1)];
            const float* srow = buf + k * C_DIM;
            float4 v;
            v.x = srow[bj.x]; v.y = srow[bj.y]; v.z = srow[bj.z]; v.w = srow[bj.w];
            __stwt(((float4*)out) + (size_t)orow * (C_DIM / 4) + c4, v);
        }
        __syncthreads();   // buffer fully consumed

        if (tid == 0 && c + 2 < CHUNKS) {
            mbar_expect_tx(mb, CHUNK_BYTES);
            bulk_ld(sbase + (c & 1) * CHUNK_BYTES,
                    x + (size_t)(q0 + (c + 2) * CHUNK_ROWS) * C_DIM,
                    CHUNK_BYTES, mb);
        }
    }
}

extern "C" void kernel_launch(void* const* d_in, const int* in_sizes, int n_in,
                              void* d_out, int out_size) {
    const float* x  = (const float*)d_in[0];   // [16, 1024, 2048] f32
    const float* wc = (const float*)d_in[1];   // [2048] f32
    const float* wr = (const float*)d_in[2];   // [1024] f32
    float* out = (float*)d_out;

    cudaFuncSetAttribute(fused_kernel,
                         cudaFuncAttributeMaxDynamicSharedMemorySize, SMEM_TOTAL);
    const int grid = 2 + (B_DIM * R_DIM) / ROWS_PER_BLOCK;   // 1026
    fused_kernel<<<grid, 1024, SMEM_TOTAL>>>(x, wc, wr, out);
}

// round 7
// speedup vs baseline: 1.5056x; 1.0260x over previous
#include <cuda_runtime.h>
#include <cuda_bf16.h>
#include <cstdint>

#define C_DIM 2048
#define R_DIM 1024
#define B_DIM 16

#define ROWS_PER_BLOCK 16
#define CHUNK_ROWS 2
#define NCHUNKS (ROWS_PER_BLOCK / CHUNK_ROWS)      /* 8 */
#define NBUF 4
#define CHUNK_BYTES (CHUNK_ROWS * C_DIM * 4)       /* 16384 */
#define SMEM_TOTAL (NBUF * CHUNK_BYTES + 64)       /* 4 buffers + mbarriers */

// Device-global scratch (no allocations allowed)
__device__ int g_sel_b[C_DIM];   // out col j reads input col g_sel_b[j]
__device__ int g_inv_r[R_DIM];   // input row q goes to output row g_inv_r[q]
__device__ int g_flag[2];        // prep-done flags (col, row); idempotent 0->1

// ---------------- PTX helpers ----------------
__device__ __forceinline__ uint32_t smem_u32(const void* p) {
    return (uint32_t)__cvta_generic_to_shared(p);
}
__device__ __forceinline__ void mbar_init(uint32_t a, uint32_t cnt) {
    asm volatile("mbarrier.init.shared.b64 [%0], %1;" :: "r"(a), "r"(cnt) : "memory");
}
__device__ __forceinline__ void mbar_expect_tx(uint32_t a, uint32_t bytes) {
    asm volatile("mbarrier.arrive.expect_tx.shared.b64 _, [%0], %1;"
                 :: "r"(a), "r"(bytes) : "memory");
}
__device__ __forceinline__ void mbar_wait(uint32_t a, uint32_t parity) {
    asm volatile(
        "{\n\t.reg .pred P;\n\t"
        "WAIT_%=:\n\t"
        "mbarrier.try_wait.parity.acquire.cta.shared::cta.b64 P, [%0], %1, 0x989680;\n\t"
        "@P bra.uni DONE_%=;\n\t"
        "bra.uni WAIT_%=;\n\t"
        "DONE_%=:\n\t}"
        :: "r"(a), "r"(parity) : "memory");
}
__device__ __forceinline__ void bulk_ld(uint32_t dst, const void* src,
                                        uint32_t bytes, uint32_t mbar) {
    asm volatile(
        "cp.async.bulk.shared::cluster.global.mbarrier::complete_tx::bytes [%0], [%1], %2, [%3];"
        :: "r"(dst), "l"(src), "r"(bytes), "r"(mbar) : "memory");
}

// ---------------- block-wide inclusive scan (1024 threads) ----------------
__device__ __forceinline__ void block_scan(int* a, int n, int tid, int* wsum) {
    const int lane = tid & 31, wid = tid >> 5;
    int v0 = 0, v1 = 0;
    const int i0 = 2 * tid;
    if (n == 2048) { v0 = a[i0]; v1 = a[i0 + 1]; }
    else           { v0 = a[tid]; }
    int s = v0 + v1;
    #pragma unroll
    for (int off = 1; off < 32; off <<= 1) {
        int y = __shfl_up_sync(0xffffffffu, s, off);
        if (lane >= off) s += y;
    }
    if (lane == 31) wsum[wid] = s;
    __syncthreads();
    if (wid == 0) {
        int t = wsum[lane];
        #pragma unroll
        for (int off = 1; off < 32; off <<= 1) {
            int y = __shfl_up_sync(0xffffffffu, t, off);
            if (lane >= off) t += y;
        }
        wsum[lane] = t;
    }
    __syncthreads();
    const int excl = (wid ? wsum[wid - 1] : 0) + s - (v0 + v1);
    if (n == 2048) { a[i0] = excl + v0; a[i0 + 1] = excl + v0 + v1; }
    else           { a[tid] = excl + v0; }
    __syncthreads();
}

// ---------------------------------------------------------------------------
// Fused kernel. Blocks 0,1: prep (dedup indices). Blocks 2..: TMA-pipelined
// row-scatter / column-gather with a 4-deep 16KB-chunk pipeline. Gather
// blocks front-issue 4 bulk loads (they depend only on fixed input rows),
// then wait for the prep flags before the store phase.
// ---------------------------------------------------------------------------
__global__ void __launch_bounds__(1024, 2)
fused_kernel(const float* __restrict__ x, const float* __restrict__ wc,
             const float* __restrict__ wr, float* __restrict__ out)
{
    extern __shared__ char smem[];
    const int tid = threadIdx.x;

    if (blockIdx.x < 2) {
        // ================= PREP =================
        const bool  isC = (blockIdx.x == 0);
        const int   n   = isC ? C_DIM : R_DIM;
        const float* w  = isC ? wc : wr;

        int* sel         = (int*)smem;
        int* firstIdx    = sel + C_DIM;
        int* scanA       = firstIdx + C_DIM;
        int* emptyByRank = scanA + C_DIM;
        __shared__ int wsum[32];
        __shared__ int sh_E;

        const float upper = (float)(n - 1);
        if (n == 2048) {
            const int i0 = 2 * tid;
            sel[i0]     = __float2int_rn(fminf(fmaxf(w[i0],     0.0f), upper));
            sel[i0 + 1] = __float2int_rn(fminf(fmaxf(w[i0 + 1], 0.0f), upper));
            firstIdx[i0] = 0x7fffffff; firstIdx[i0 + 1] = 0x7fffffff;
        } else {
            sel[tid] = __float2int_rn(fminf(fmaxf(w[tid], 0.0f), upper));
            firstIdx[tid] = 0x7fffffff;
        }
        __syncthreads();
        for (int i = tid; i < n; i += 1024) atomicMin(&firstIdx[sel[i]], i);
        __syncthreads();

        // pass 1: scan EMPTY flags over values -> emptyByRank (descending)
        for (int v = tid; v < n; v += 1024)
            scanA[v] = (firstIdx[v] == 0x7fffffff) ? 1 : 0;
        __syncthreads();
        block_scan(scanA, n, tid, wsum);
        if (tid == 0) sh_E = scanA[n - 1];
        __syncthreads();
        const int E = sh_E;
        for (int v = tid; v < n; v += 1024) {
            if (firstIdx[v] == 0x7fffffff) {
                int asc = scanA[v] - 1;
                emptyByRank[E - 1 - asc] = v;   // slot 0 = largest empty value
            }
        }
        __syncthreads();

        // pass 2: scan DUP flags over indices -> duplicate rank
        for (int i = tid; i < n; i += 1024)
            scanA[i] = (firstIdx[sel[i]] != i) ? 1 : 0;
        __syncthreads();
        block_scan(scanA, n, tid, wsum);

        for (int i = tid; i < n; i += 1024) {
            bool dup = (firstIdx[sel[i]] != i);
            int v = dup ? emptyByRank[scanA[i] - 1] : sel[i];
            if (isC) g_sel_b[i] = v;     // column gather index
            else     g_inv_r[v] = i;     // inverse row permutation (v is a perm)
        }
        __threadfence();
        __syncthreads();
        if (tid == 0) {
            int* f = &g_flag[isC ? 0 : 1];
            asm volatile("st.release.gpu.global.b32 [%0], %1;"
                         :: "l"(f), "r"(1) : "memory");
        }
        return;
    }

    // ================= GATHER / SCATTER =================
    const int q0 = (int)(blockIdx.x - 2) * ROWS_PER_BLOCK;   // first input row
    const uint32_t sbase = smem_u32(smem);
    const uint32_t mbarb = sbase + NBUF * CHUNK_BYTES;

    if (tid == 0) {
        #pragma unroll
        for (int p = 0; p < NBUF; p++) mbar_init(mbarb + 8 * p, 1);
        asm volatile("fence.proxy.async.shared::cta;" ::: "memory");
        // Prologue: 4 chunks (64KB) in flight before anything else.
        #pragma unroll
        for (int p = 0; p < NBUF; p++) {
            mbar_expect_tx(mbarb + 8 * p, CHUNK_BYTES);
            bulk_ld(sbase + p * CHUNK_BYTES,
                    x + (size_t)(q0 + p * CHUNK_ROWS) * C_DIM,
                    CHUNK_BYTES, mbarb + 8 * p);
        }
        // Wait for prep (overlapped with the loads above).
        int a, b;
        do {
            asm volatile("ld.acquire.gpu.global.b32 %0, [%1];" : "=r"(a) : "l"(&g_flag[0]));
            asm volatile("ld.acquire.gpu.global.b32 %0, [%1];" : "=r"(b) : "l"(&g_flag[1]));
        } while (!(a && b));
    }
    __syncthreads();

    // Fixed per-thread slot: row k within chunk (0/1), float4 column c4.
    const int c4 = tid & 511;
    const int k  = tid >> 9;
    const int4 bj = ((const int4*)g_sel_b)[c4];    // reused across all chunks

    #pragma unroll
    for (int c = 0; c < NCHUNKS; c++) {
        const int buf_i = c & (NBUF - 1);
        const uint32_t mb = mbarb + 8 * buf_i;
        mbar_wait(mb, (c >> 2) & 1);
        const float* srow = (const float*)(smem + buf_i * CHUNK_BYTES) + k * C_DIM;

        const int Q = q0 + c * CHUNK_ROWS + k;               // input row (flat)
        const int orow = (Q & ~(R_DIM - 1)) | g_inv_r[Q & (R_DIM - 1)];
        float4 v;
        v.x = srow[bj.x]; v.y = srow[bj.y]; v.z = srow[bj.z]; v.w = srow[bj.w];
        __stwt(((float4*)out) + (size_t)orow * (C_DIM / 4) + c4, v);

        __syncthreads();   // buffer fully consumed by all threads

        if (tid == 0 && c + NBUF < NCHUNKS) {
            mbar_expect_tx(mb, CHUNK_BYTES);
            bulk_ld(sbase + buf_i * CHUNK_BYTES,
                    x + (size_t)(q0 + (c + NBUF) * CHUNK_ROWS) * C_DIM,
                    CHUNK_BYTES, mb);
        }
    }
}

extern "C" void kernel_launch(void* const* d_in, const int* in_sizes, int n_in,
                              void* d_out, int out_size) {
    const float* x  = (const float*)d_in[0];   // [16, 1024, 2048] f32
    const float* wc = (const float*)d_in[1];   // [2048] f32
    const float* wr = (const float*)d_in[2];   // [1024] f32
    float* out = (float*)d_out;

    cudaFuncSetAttribute(fused_kernel,
                         cudaFuncAttributeMaxDynamicSharedMemorySize, SMEM_TOTAL);
    const int grid = 2 + (B_DIM * R_DIM) / ROWS_PER_BLOCK;   // 1026
    fused_kernel<<<grid, 1024, SMEM_TOTAL>>>(x, wc, wr, out);
}